// round 17
// baseline (speedup 1.0000x reference)
#include <cuda_runtime.h>

#define NPLANES 32
#define HW 65536
#define PR 32                         // vertical pad rows (>= max W)
#define PPL ((256 + 2 * PR) * 256)    // padded plane size in floats
#define SROW 368                      // skewed smem row stride (floats)

// A: y-padded H-dilate result (pads -1e4).  C: y-padded H-erode result (pads +1e4).
static __device__ float g_bufA[4 * NPLANES * PPL];
static __device__ float g_bufC[4 * NPLANES * PPL];

// ---------------------------------------------------------------------------
// hsweep2: source-centric horizontal weighted opt over TWO skewed smem rows
// simultaneously (2 independent LDS/dep-chain streams per thread for ILP).
//   acc[i] = opt_j tile[x0+i+j] + c2*se(j), se(j)=j^2*2^-TL exact dyadic,
//   FFMA-imm form (se compile-time, multiplier immediate).
// base* = s + row*SROW + x0 + (x0>>3), x0 multiple of 8 so the skew
// decomposes per unrolled u: ind(x0+u) = ind(x0) + u + (u>>3).
// ---------------------------------------------------------------------------
template <int W, int TL, bool ISMAX>
__device__ __forceinline__ void hsweep2(const float* __restrict__ base0,
                                        const float* __restrict__ base1,
                                        float c2,
                                        float* __restrict__ acc0,
                                        float* __restrict__ acc1)
{
    constexpr float SESC = 1.0f / (float)(1 << TL);
#pragma unroll
    for (int u = 0; u < 2 * W + 8; ++u) {
        const float v0 = base0[u + (u >> 3)];
        const float v1 = base1[u + (u >> 3)];
#pragma unroll
        for (int i = 0; i < 8; ++i) {
            const int j = u - W - i;
            if (j >= -W && j <= W) {
                const float jw = (float)(j * j) * SESC;
                const float c0 = fmaf(c2, jw, v0);
                const float c1 = fmaf(c2, jw, v1);
                acc0[i] = ISMAX ? fmaxf(acc0[i], c0) : fminf(acc0[i], c0);
                acc1[i] = ISMAX ? fmaxf(acc1[i], c1) : fminf(acc1[i], c1);
            }
        }
    }
}

// ---------------------------------------------------------------------------
// K1 body: H-dilate one scale, 16-row tile. Stage (batched LDG, high MLP),
// then each thread sweeps rows r and r+8.
// ---------------------------------------------------------------------------
template <int W, int TL>
__device__ __forceinline__ void hdil_body(float* __restrict__ s,
                                          const float* __restrict__ sp,
                                          float* __restrict__ dp,
                                          float c2, int t)
{
    constexpr int RW = 256 + 2 * W;
    for (int p = t; p < RW; p += 256) {
        const int xx = p - W;
        const bool inb = ((unsigned)xx < 256u);
        const int si = p + (p >> 3);
#pragma unroll
        for (int rr = 0; rr < 16; rr++) {
            s[rr * SROW + si] = inb ? sp[rr * 256 + xx] : -10000.0f;
        }
    }
    __syncthreads();

    const int r  = t >> 5;
    const int x0 = (t & 31) * 8;
    const float* base0 = s + r * SROW + x0 + (x0 >> 3);
    const float* base1 = s + (r + 8) * SROW + x0 + (x0 >> 3);

    float acc0[8], acc1[8];
#pragma unroll
    for (int i = 0; i < 8; i++) { acc0[i] = -3.0e38f; acc1[i] = -3.0e38f; }
    hsweep2<W, TL, true>(base0, base1, c2, acc0, acc1);

    float* d0 = dp + r * 256 + x0;
    float* d1 = dp + (r + 8) * 256 + x0;
    *(float4*)(d0 + 0) = make_float4(acc0[0], acc0[1], acc0[2], acc0[3]);
    *(float4*)(d0 + 4) = make_float4(acc0[4], acc0[5], acc0[6], acc0[7]);
    *(float4*)(d1 + 0) = make_float4(acc1[0], acc1[1], acc1[2], acc1[3]);
    *(float4*)(d1 + 4) = make_float4(acc1[4], acc1[5], acc1[6], acc1[7]);
}

__global__ __launch_bounds__(256, 4) void hdil_all(const float* __restrict__ in,
                                                   float* __restrict__ Apad,
                                                   const float* __restrict__ coefp)
{
    __shared__ float s[16 * SROW];
    const int g = blockIdx.x;          // 0..19: 16 row-groups + 4 pad-fill groups
    const int scale = blockIdx.z;
    const int plane = blockIdx.y;
    const int t = threadIdx.x;
    float* dplane = Apad + (size_t)(scale * NPLANES + plane) * PPL;

    if (g >= 16) {                     // fill this scale's vertical pad rows
        const int pr = (g - 16) * 16;                   // 0..63
        const int prow = (pr < PR) ? pr : (pr + 256);
        const float4 pv = make_float4(-10000.0f, -10000.0f, -10000.0f, -10000.0f);
        for (int idx = t; idx < 16 * 64; idx += 256) {
            int rr = idx >> 6, cc = idx & 63;
            *(float4*)(dplane + (prow + rr) * 256 + cc * 4) = pv;
        }
        return;
    }

    const float c2 = -__ldg(coefp);
    const int rowbase = g * 16;
    const float* sp = in + plane * HW + rowbase * 256;
    float* dp = dplane + (PR + rowbase) * 256;

    if      (scale == 0) hdil_body< 4, 2>(s, sp, dp, c2, t);
    else if (scale == 1) hdil_body< 8, 4>(s, sp, dp, c2, t);
    else if (scale == 2) hdil_body<16, 6>(s, sp, dp, c2, t);
    else                 hdil_body<32, 8>(s, sp, dp, c2, t);
}

// ---------------------------------------------------------------------------
// vsweep4: source-centric vertical weighted opt, float4 (4 cols), NR rows.
// One LDG.128 per source row covers 4 columns.
// ---------------------------------------------------------------------------
template <int W, int TL, bool ISMAX, int NR>
__device__ __forceinline__ void vsweep4(const float* __restrict__ sp, // plane + x
                                        float c2, float4* __restrict__ acc, int y0)
{
    constexpr float SESC = 1.0f / (float)(1 << TL);
#pragma unroll
    for (int u = 0; u < 2 * W + NR; ++u) {
        const float4 v = *(const float4*)(sp + (y0 - W + u) * 256);
#pragma unroll
        for (int i = 0; i < NR; ++i) {
            const int j = u - W - i;
            if (j >= -W && j <= W) {
                const float jw = (float)(j * j) * SESC;
                const float cx = fmaf(c2, jw, v.x);
                const float cy = fmaf(c2, jw, v.y);
                const float cz = fmaf(c2, jw, v.z);
                const float cw = fmaf(c2, jw, v.w);
                acc[i].x = ISMAX ? fmaxf(acc[i].x, cx) : fminf(acc[i].x, cx);
                acc[i].y = ISMAX ? fmaxf(acc[i].y, cy) : fminf(acc[i].y, cy);
                acc[i].z = ISMAX ? fmaxf(acc[i].z, cz) : fminf(acc[i].z, cz);
                acc[i].w = ISMAX ? fmaxf(acc[i].w, cw) : fminf(acc[i].w, cw);
            }
        }
    }
}

// ---------------------------------------------------------------------------
// K2 body: fused V-dilate (padded A -> smem 16-row strip, float4) then
// H-erode (smem -> C). V-phase: thread = 4 cols x 4 rows (4 y-groups).
// ---------------------------------------------------------------------------
template <int W, int TL>
__device__ __forceinline__ void k2body(const float* __restrict__ Apl,
                                       float* __restrict__ s,
                                       float* __restrict__ Cpl,
                                       float cdil, float cero,
                                       int t, int ytile)
{
    // ---- V-dilate: thread = 4 cols x 4 rows ----
    {
        const int x  = (t & 63) * 4;
        const int lg = t >> 6;                   // y-group 0..3
        const int y0 = ytile + lg * 4;
        float4 acc[4];
#pragma unroll
        for (int i = 0; i < 4; i++)
            acc[i] = make_float4(-3.0e38f, -3.0e38f, -3.0e38f, -3.0e38f);
        vsweep4<W, TL, true, 4>(Apl + x, cdil, acc, y0);

        // park in skewed smem at p = 32 + x (p multiple of 4: stays in skew block)
        const int p = 32 + x;
#pragma unroll
        for (int i = 0; i < 4; i++) {
            const int bi = (lg * 4 + i) * SROW + p + (p >> 3);
            s[bi]     = acc[i].x;
            s[bi + 1] = acc[i].y;
            s[bi + 2] = acc[i].z;
            s[bi + 3] = acc[i].w;
        }
    }

    // x-pads for the 16 rows: cols [0,32) and [288,320) = +1e4 (erosion pad)
    for (int idx = t; idx < 16 * 64; idx += 256) {
        int rr = idx >> 6, cc = idx & 63;
        int p = (cc < 32) ? cc : (cc + 256);
        s[rr * SROW + p + (p >> 3)] = 10000.0f;
    }
    __syncthreads();

    // ---- H-erode from smem: thread = 8 cols x 2 rows (r, r+8), dual sweep ----
    // Staged tile has uniform pad 32; sweep base offset b0 = x0 + (32 - W).
    {
        const int r  = t >> 5;
        const int x0 = (t & 31) * 8;
        const int b0 = x0 + (32 - W);
        const float* base0 = s + r * SROW;
        const float* base1 = s + (r + 8) * SROW;

        float acc0[8], acc1[8];
#pragma unroll
        for (int i = 0; i < 8; i++) { acc0[i] = 3.0e38f; acc1[i] = 3.0e38f; }

        constexpr float SESC = 1.0f / (float)(1 << TL);
#pragma unroll
        for (int u = 0; u < 2 * W + 8; ++u) {
            const int pp = b0 + u;               // b0 + u: skew fully recomputed
            const float v0 = base0[pp + (pp >> 3)];
            const float v1 = base1[pp + (pp >> 3)];
#pragma unroll
            for (int i = 0; i < 8; ++i) {
                const int j = u - W - i;
                if (j >= -W && j <= W) {
                    const float jw = (float)(j * j) * SESC;
                    const float c0 = fmaf(cero, jw, v0);
                    const float c1 = fmaf(cero, jw, v1);
                    acc0[i] = fminf(acc0[i], c0);
                    acc1[i] = fminf(acc1[i], c1);
                }
            }
        }

        float* d0 = Cpl + (size_t)(ytile + r) * 256 + x0;
        float* d1 = Cpl + (size_t)(ytile + r + 8) * 256 + x0;
        *(float4*)(d0 + 0) = make_float4(acc0[0], acc0[1], acc0[2], acc0[3]);
        *(float4*)(d0 + 4) = make_float4(acc0[4], acc0[5], acc0[6], acc0[7]);
        *(float4*)(d1 + 0) = make_float4(acc1[0], acc1[1], acc1[2], acc1[3]);
        *(float4*)(d1 + 4) = make_float4(acc1[4], acc1[5], acc1[6], acc1[7]);
    }
}

__global__ __launch_bounds__(256, 4) void vdil_hero_all(const float* __restrict__ Apad,
                                                        float* __restrict__ Cpad,
                                                        const float* __restrict__ coefp)
{
    __shared__ float s[16 * SROW];
    const int scale = blockIdx.z;
    const int plane = blockIdx.y;
    const int gx = blockIdx.x;         // 0..19: 16 strips + 4 pad-fill groups
    const int t = threadIdx.x;
    float* Cpl = Cpad + (size_t)(scale * NPLANES + plane) * PPL;

    if (gx >= 16) {                    // fill C's vertical pad rows (+1e4)
        const int pr = (gx - 16) * 16;
        const int prow = (pr < PR) ? pr : (pr + 256);
        const float4 pv = make_float4(10000.0f, 10000.0f, 10000.0f, 10000.0f);
        for (int idx = t; idx < 16 * 64; idx += 256) {
            int rr = idx >> 6, cc = idx & 63;
            *(float4*)(Cpl + (prow + rr) * 256 + cc * 4) = pv;
        }
        return;
    }

    const float c = __ldg(coefp);
    const float* Apl = Apad + (size_t)(scale * NPLANES + plane) * PPL + PR * 256;
    float* CplD = Cpl + PR * 256;
    const int ytile = gx * 16;

    if      (scale == 0) k2body< 4, 2>(Apl, s, CplD, -c, c, t, ytile);
    else if (scale == 1) k2body< 8, 4>(Apl, s, CplD, -c, c, t, ytile);
    else if (scale == 2) k2body<16, 6>(Apl, s, CplD, -c, c, t, ytile);
    else                 k2body<32, 8>(Apl, s, CplD, -c, c, t, ytile);
}

// ---------------------------------------------------------------------------
// K3: V-erode (padded C -> stacked output), float4, thread = 4 cols x 8 rows.
// Block covers 32 rows (4 y-groups); grid x = 8.
// ---------------------------------------------------------------------------
template <int W, int TL>
__device__ __forceinline__ void vero_body(const float* __restrict__ sp,
                                          float* __restrict__ dp,
                                          float c2, int y0)
{
    float4 acc[8];
#pragma unroll
    for (int i = 0; i < 8; i++)
        acc[i] = make_float4(3.0e38f, 3.0e38f, 3.0e38f, 3.0e38f);
    vsweep4<W, TL, false, 8>(sp, c2, acc, y0);
#pragma unroll
    for (int i = 0; i < 8; i++)
        *(float4*)(dp + i * 256) = acc[i];
}

__global__ __launch_bounds__(256, 4) void vero_all(const float* __restrict__ Cpad,
                                                   float* __restrict__ dst,
                                                   const float* __restrict__ coefp)
{
    const int scale = blockIdx.z;
    const int plane = blockIdx.y;
    const int t = threadIdx.x;
    const int x  = (t & 63) * 4;
    const int y0 = blockIdx.x * 32 + (t >> 6) * 8;
    const float c2 = __ldg(coefp);

    const float* sp = Cpad + (size_t)(scale * NPLANES + plane) * PPL + PR * 256 + x;
    float* dp = dst + (size_t)scale * HW + (size_t)plane * 4 * HW + y0 * 256 + x;

    if      (scale == 0) vero_body< 4, 2>(sp, dp, c2, y0);
    else if (scale == 1) vero_body< 8, 4>(sp, dp, c2, y0);
    else if (scale == 2) vero_body<16, 6>(sp, dp, c2, y0);
    else                 vero_body<32, 8>(sp, dp, c2, y0);
}

// ---------------------------------------------------------------------------
// 3 launches: H-dil (in->A) -> fused V-dil+H-ero (A->C) -> V-ero (C->out)
// ---------------------------------------------------------------------------
extern "C" void kernel_launch(void* const* d_in, const int* in_sizes, int n_in,
                              void* d_out, int out_size)
{
    (void)in_sizes; (void)n_in; (void)out_size;
    const float* in   = (const float*)d_in[0];
    const float* coef = (const float*)d_in[1];
    float* out = (float*)d_out;

    float *A = nullptr, *C = nullptr;
    cudaGetSymbolAddress((void**)&A, g_bufA);
    cudaGetSymbolAddress((void**)&C, g_bufC);

    dim3 g1(20, NPLANES, 4);     // 16 row-groups (16 rows) + 4 pad-fill groups
    dim3 g2(20, NPLANES, 4);     // 16 strips + 4 pad-fill groups
    dim3 g3(8,  NPLANES, 4);     // 8 y-groups of 32 rows

    hdil_all     <<<g1, 256>>>(in, A, coef);
    vdil_hero_all<<<g2, 256>>>(A, C, coef);
    vero_all     <<<g3, 256>>>(C, out, coef);
}